// round 13
// baseline (speedup 1.0000x reference)
#include <cuda_runtime.h>
#include <math.h>
#include <string.h>

#define S_LEN 512
#define B_SZ  256
#define E_DIM 128
#define H_DIM 256

static __device__ float g_xproj[(size_t)S_LEN * B_SZ * H_DIM];

typedef unsigned long long ull;

__device__ __forceinline__ void ffma2(ull& d, ull a, ull b) {
    asm("fma.rn.f32x2 %0, %1, %2, %0;" : "+l"(d) : "l"(a), "l"(b));
}
__device__ __forceinline__ ull dup2(float w) {
    ull p;
    asm("mov.b64 %0, {%1, %1};" : "=l"(p) : "f"(w));
    return p;
}
__device__ __forceinline__ float2 as_f2(ull v) {
    float2 f; memcpy(&f, &v, 8); return f;
}
__device__ __forceinline__ float tanh_fast(float x) {
    float y;
    asm("tanh.approx.f32 %0, %1;" : "=f"(y) : "f"(x));
    return y;
}

// ---------------------------------------------------------------------------
// Kernel 1: fused gather + input projection, 128x128-tile GEMM (proven R8).
// grid = (1024, 2). 256 threads, 8x8 fragment each, As/Bs k-major in smem.
// ---------------------------------------------------------------------------
__global__ void __launch_bounds__(256, 1) xproj_kernel(
    const int* __restrict__ X, const float* __restrict__ emb,
    const float* __restrict__ W_ih, const float* __restrict__ b_ih,
    const float* __restrict__ b_hh)
{
    extern __shared__ __align__(16) float xsm[];
    float* As = xsm;                  // [k][m] 128x128
    float* Bs = xsm + 128 * 128;      // [k][n] 128x128
    int*   ids = (int*)(Bs + 128 * 128);

    const int t  = threadIdx.x;
    const int m0 = blockIdx.x * 128;
    const int n0 = blockIdx.y * 128;

    if (t < 128) ids[t] = X[m0 + t];
    __syncthreads();

#pragma unroll
    for (int it = 0; it < 16; it++) {
        int idx = t + 256 * it;
        int rr = idx & 127, q = idx >> 7;
        float4 fa = ((const float4*)(emb + (size_t)ids[rr] * E_DIM))[q];
        As[(4 * q + 0) * 128 + rr] = fa.x;
        As[(4 * q + 1) * 128 + rr] = fa.y;
        As[(4 * q + 2) * 128 + rr] = fa.z;
        As[(4 * q + 3) * 128 + rr] = fa.w;
        float4 fb = ((const float4*)(W_ih + (size_t)(n0 + rr) * E_DIM))[q];
        Bs[(4 * q + 0) * 128 + rr] = fb.x;
        Bs[(4 * q + 1) * 128 + rr] = fb.y;
        Bs[(4 * q + 2) * 128 + rr] = fb.z;
        Bs[(4 * q + 3) * 128 + rr] = fb.w;
    }
    __syncthreads();

    const int tx = t & 15, ty = t >> 4;

    ull acc[32];
#pragma unroll
    for (int i = 0; i < 32; i++) acc[i] = 0ULL;

#pragma unroll 4
    for (int k = 0; k < 128; k++) {
        float4 a0 = *(const float4*)(As + k * 128 + ty * 8);
        float4 a1 = *(const float4*)(As + k * 128 + ty * 8 + 4);
        ulonglong2 bl = *(const ulonglong2*)(Bs + k * 128 + tx * 8);
        ulonglong2 bh = *(const ulonglong2*)(Bs + k * 128 + tx * 8 + 4);
        float am[8] = {a0.x, a0.y, a0.z, a0.w, a1.x, a1.y, a1.z, a1.w};
#pragma unroll
        for (int m = 0; m < 8; m++) {
            ull ad = dup2(am[m]);
            ffma2(acc[m * 4 + 0], bl.x, ad);
            ffma2(acc[m * 4 + 1], bl.y, ad);
            ffma2(acc[m * 4 + 2], bh.x, ad);
            ffma2(acc[m * 4 + 3], bh.y, ad);
        }
    }

    float bias[8];
#pragma unroll
    for (int j = 0; j < 8; j++) {
        int n = n0 + tx * 8 + j;
        bias[j] = b_ih[n] + b_hh[n];
    }
#pragma unroll
    for (int m = 0; m < 8; m++) {
        float o[8];
#pragma unroll
        for (int p = 0; p < 4; p++) {
            float2 f = as_f2(acc[m * 4 + p]);
            o[2 * p]     = f.x + bias[2 * p];
            o[2 * p + 1] = f.y + bias[2 * p + 1];
        }
        float* dst = g_xproj + (size_t)(m0 + ty * 8 + m) * H_DIM + n0 + tx * 8;
        *(float4*)(dst)     = make_float4(o[0], o[1], o[2], o[3]);
        *(float4*)(dst + 4) = make_float4(o[4], o[5], o[6], o[7]);
    }
}

// ---------------------------------------------------------------------------
// Kernel 2: 512-step recurrence + fused log_softmax.
// 256 threads, 2 batch rows per CTA (grid 128). Thread t = output o.
//   W_hh[o][0..192)   -> 192 registers (96 ull j-pairs)
//   W_hh[o][192..256) -> smem (16 ulonglong2/thread, lane-consecutive)
// Phased step to overlap the serial tail:
//   1) row-A register-j section
//   2) shared smem-W section (both rows, Wsm loaded once)
//   3) finalize row A (tanh.approx + STS) -- overlaps --
//   4) row-B register-j section
//   5) finalize row B, ONE barrier.
// ---------------------------------------------------------------------------
__global__ void __launch_bounds__(256, 1) rnn_kernel(
    const float* __restrict__ W_hh, float* __restrict__ out)
{
    extern __shared__ __align__(16) float sm[];
    ulonglong2* Wsm = (ulonglong2*)sm;   // [16][256] ulonglong2 = 64 KB
    float* hbuf = sm + 16384;            // [2 buf][2 row][256] = 1024 floats
    float* red  = hbuf + 1024;           // [256]

    const int t  = threadIdx.x;          // = output index o
    const int b0 = blockIdx.x * 2;

    const ulonglong2* wr = (const ulonglong2*)(W_hh + (size_t)t * H_DIM);

    // j in [0,192): 48 ulonglong2 -> 96 ull register pairs (192 GPRs)
    ull Wp[96];
#pragma unroll
    for (int c = 0; c < 48; c++) {
        ulonglong2 v = wr[c];
        Wp[2 * c] = v.x; Wp[2 * c + 1] = v.y;
    }
    // j in [192,256): 16 ulonglong2 -> smem, lane-consecutive layout
#pragma unroll
    for (int c = 0; c < 16; c++) Wsm[c * 256 + t] = wr[48 + c];

    hbuf[t] = 0.0f;          // buf0 row A
    hbuf[256 + t] = 0.0f;    // buf0 row B
    __syncthreads();

    const float* xpA = g_xproj + (size_t)b0 * H_DIM + t;
    const float* xpB = xpA + H_DIM;
    float xvA = xpA[0];
    float xvB = xpB[0];

    for (int s = 0; s < S_LEN; s++) {
        float xnA = 0.0f, xnB = 0.0f;
        if (s + 1 < S_LEN) {
            size_t off = (size_t)(s + 1) * (B_SZ * H_DIM);
            xnA = xpA[off];
            xnB = xpB[off];
        }

        const ulonglong2* hA = (const ulonglong2*)(hbuf + (s & 1) * 512);
        const ulonglong2* hB = (const ulonglong2*)(hbuf + (s & 1) * 512 + 256);
        float* hn = hbuf + ((s + 1) & 1) * 512;

        ull a0 = 0ULL, a1 = 0ULL, a2 = 0ULL, a3 = 0ULL;

        // (1) row A, register-W j in [0,192)
#pragma unroll
        for (int c = 0; c < 48; c++) {
            ulonglong2 ha = hA[c];
            ffma2(a0, Wp[2 * c],     ha.x);
            ffma2(a1, Wp[2 * c + 1], ha.y);
        }
        // (2) shared smem-W section, j in [192,256): both rows, Wsm read once
#pragma unroll
        for (int c = 0; c < 16; c++) {
            ulonglong2 wv = Wsm[c * 256 + t];
            ulonglong2 ha = hA[48 + c];
            ulonglong2 hb = hB[48 + c];
            ffma2(a0, wv.x, ha.x);
            ffma2(a1, wv.y, ha.y);
            ffma2(a2, wv.x, hb.x);
            ffma2(a3, wv.y, hb.y);
        }
        // (3) finalize row A — MUFU tanh overlaps section (4)
        {
            float2 f0 = as_f2(a0), f1 = as_f2(a1);
            float hnA = tanh_fast(xvA + ((f0.x + f0.y) + (f1.x + f1.y)));
            hn[t] = hnA;
        }
        // (4) row B, register-W j in [0,192)
#pragma unroll
        for (int c = 0; c < 48; c++) {
            ulonglong2 hb = hB[c];
            ffma2(a2, Wp[2 * c],     hb.x);
            ffma2(a3, Wp[2 * c + 1], hb.y);
        }
        // (5) finalize row B
        {
            float2 f2 = as_f2(a2), f3 = as_f2(a3);
            float hnB = tanh_fast(xvB + ((f2.x + f2.y) + (f3.x + f3.y)));
            hn[256 + t] = hnB;
        }
        __syncthreads();       // single barrier per step

        xvA = xnA;
        xvB = xnB;
    }

    // Final h in buffer 0 (S_LEN even). Fused log_softmax per row.
    for (int r = 0; r < 2; r++) {
        float x = hbuf[r * 256 + t];

        red[t] = x;
        __syncthreads();
        for (int off = 128; off > 0; off >>= 1) {
            if (t < off) red[t] = fmaxf(red[t], red[t + off]);
            __syncthreads();
        }
        float mx = red[0];
        __syncthreads();

        red[t] = expf(x - mx);
        __syncthreads();
        for (int off = 128; off > 0; off >>= 1) {
            if (t < off) red[t] = red[t] + red[t + off];
            __syncthreads();
        }
        float lse = logf(red[0]);
        __syncthreads();

        out[(size_t)(b0 + r) * H_DIM + t] = x - mx - lse;
    }
}

extern "C" void kernel_launch(void* const* d_in, const int* in_sizes, int n_in,
                              void* d_out, int out_size)
{
    const int*   X    = (const int*)d_in[0];
    const float* emb  = (const float*)d_in[1];
    const float* W_ih = (const float*)d_in[2];
    const float* W_hh = (const float*)d_in[3];
    const float* b_ih = (const float*)d_in[4];
    const float* b_hh = (const float*)d_in[5];
    float* out = (float*)d_out;

    const int smem_xproj = (128 * 128 * 2) * 4 + 128 * 4;     // 131584 B
    const int smem_rnn   = 16384 * 4 + (1024 + 256) * 4;      // 70656 B
    cudaFuncSetAttribute(xproj_kernel, cudaFuncAttributeMaxDynamicSharedMemorySize, smem_xproj);
    cudaFuncSetAttribute(rnn_kernel,   cudaFuncAttributeMaxDynamicSharedMemorySize, smem_rnn);

    dim3 xgrid((S_LEN * B_SZ) / 128, 2);
    xproj_kernel<<<xgrid, 256, smem_xproj>>>(X, emb, W_ih, b_ih, b_hh);
    rnn_kernel<<<B_SZ / 2, 256, smem_rnn>>>(W_hh, out);
}

// round 14
// speedup vs baseline: 1.0047x; 1.0047x over previous
#include <cuda_runtime.h>
#include <math.h>
#include <string.h>

#define S_LEN 512
#define B_SZ  256
#define E_DIM 128
#define H_DIM 256

static __device__ float g_xproj[(size_t)S_LEN * B_SZ * H_DIM];

typedef unsigned long long ull;

__device__ __forceinline__ void ffma2(ull& d, ull a, ull b) {
    asm("fma.rn.f32x2 %0, %1, %2, %0;" : "+l"(d) : "l"(a), "l"(b));
}
__device__ __forceinline__ ull dup2(float w) {
    ull p;
    asm("mov.b64 %0, {%1, %1};" : "=l"(p) : "f"(w));
    return p;
}
__device__ __forceinline__ float2 as_f2(ull v) {
    float f0, f1;
    asm("mov.b64 {%0, %1}, %2;" : "=f"(f0), "=f"(f1) : "l"(v));
    return make_float2(f0, f1);
}
__device__ __forceinline__ float tanh_fast(float x) {
    float y;
    asm("tanh.approx.f32 %0, %1;" : "=f"(y) : "f"(x));
    return y;
}

// ---------------------------------------------------------------------------
// Kernel 1: fused gather + input projection, 128x128-tile GEMM, K staged in
// two 64-chunks so smem = 66 KB -> 2 CTAs/SM (16 warps, latency hidden).
// grid = (1024, 2): blockIdx.x = m-tile, blockIdx.y = n-half.
// 256 threads, each computes an 8m x 8n fragment.
// ---------------------------------------------------------------------------
__global__ void __launch_bounds__(256, 2) xproj_kernel(
    const int* __restrict__ X, const float* __restrict__ emb,
    const float* __restrict__ W_ih, const float* __restrict__ b_ih,
    const float* __restrict__ b_hh)
{
    extern __shared__ __align__(16) float xsm[];
    float* As = xsm;                  // [kk][m] 64x128 = 32 KB
    float* Bs = xsm + 64 * 128;       // [kk][n] 64x128 = 32 KB
    int*   ids = (int*)(Bs + 64 * 128);

    const int t  = threadIdx.x;
    const int m0 = blockIdx.x * 128;
    const int n0 = blockIdx.y * 128;

    if (t < 128) ids[t] = X[m0 + t];
    __syncthreads();

    const int tx = t & 15, ty = t >> 4;

    ull acc[32];
#pragma unroll
    for (int i = 0; i < 32; i++) acc[i] = 0ULL;

    for (int kc = 0; kc < 2; kc++) {
        // Stage this k-chunk of A (gathered emb) and B (W_ih), k-major.
        // 1024 float4 each, 4 per thread.
#pragma unroll
        for (int it = 0; it < 4; it++) {
            int idx = t + 256 * it;
            int rr = idx & 127, q16 = idx >> 7;          // q16: 0..7
            int q = kc * 16 + q16 * 2;                   // float4 index pairs
            // two float4 per (rr, it) to cover 16 q-values with 4 iterations:
            // instead do single float4 at q = kc*16 + q16 with q16 0..7 → only 8 of 16.
            // Use two explicit loads:
            float4 fa = ((const float4*)(emb + (size_t)ids[rr] * E_DIM))[kc * 16 + q16];
            As[(4 * q16 + 0) * 128 + rr] = fa.x;
            As[(4 * q16 + 1) * 128 + rr] = fa.y;
            As[(4 * q16 + 2) * 128 + rr] = fa.z;
            As[(4 * q16 + 3) * 128 + rr] = fa.w;
            float4 fa2 = ((const float4*)(emb + (size_t)ids[rr] * E_DIM))[kc * 16 + q16 + 8];
            As[(4 * (q16 + 8) + 0) * 128 + rr] = fa2.x;
            As[(4 * (q16 + 8) + 1) * 128 + rr] = fa2.y;
            As[(4 * (q16 + 8) + 2) * 128 + rr] = fa2.z;
            As[(4 * (q16 + 8) + 3) * 128 + rr] = fa2.w;
            float4 fb = ((const float4*)(W_ih + (size_t)(n0 + rr) * E_DIM))[kc * 16 + q16];
            Bs[(4 * q16 + 0) * 128 + rr] = fb.x;
            Bs[(4 * q16 + 1) * 128 + rr] = fb.y;
            Bs[(4 * q16 + 2) * 128 + rr] = fb.z;
            Bs[(4 * q16 + 3) * 128 + rr] = fb.w;
            float4 fb2 = ((const float4*)(W_ih + (size_t)(n0 + rr) * E_DIM))[kc * 16 + q16 + 8];
            Bs[(4 * (q16 + 8) + 0) * 128 + rr] = fb2.x;
            Bs[(4 * (q16 + 8) + 1) * 128 + rr] = fb2.y;
            Bs[(4 * (q16 + 8) + 2) * 128 + rr] = fb2.z;
            Bs[(4 * (q16 + 8) + 3) * 128 + rr] = fb2.w;
            (void)q;
        }
        __syncthreads();

#pragma unroll 4
        for (int k = 0; k < 64; k++) {
            float4 a0 = *(const float4*)(As + k * 128 + ty * 8);
            float4 a1 = *(const float4*)(As + k * 128 + ty * 8 + 4);
            ulonglong2 bl = *(const ulonglong2*)(Bs + k * 128 + tx * 8);
            ulonglong2 bh = *(const ulonglong2*)(Bs + k * 128 + tx * 8 + 4);
            float am[8] = {a0.x, a0.y, a0.z, a0.w, a1.x, a1.y, a1.z, a1.w};
#pragma unroll
            for (int m = 0; m < 8; m++) {
                ull ad = dup2(am[m]);
                ffma2(acc[m * 4 + 0], bl.x, ad);
                ffma2(acc[m * 4 + 1], bl.y, ad);
                ffma2(acc[m * 4 + 2], bh.x, ad);
                ffma2(acc[m * 4 + 3], bh.y, ad);
            }
        }
        __syncthreads();
    }

    float bias[8];
#pragma unroll
    for (int j = 0; j < 8; j++) {
        int n = n0 + tx * 8 + j;
        bias[j] = b_ih[n] + b_hh[n];
    }
#pragma unroll
    for (int m = 0; m < 8; m++) {
        float o[8];
#pragma unroll
        for (int p = 0; p < 4; p++) {
            float2 f = as_f2(acc[m * 4 + p]);
            o[2 * p]     = f.x + bias[2 * p];
            o[2 * p + 1] = f.y + bias[2 * p + 1];
        }
        float* dst = g_xproj + (size_t)(m0 + ty * 8 + m) * H_DIM + n0 + tx * 8;
        *(float4*)(dst)     = make_float4(o[0], o[1], o[2], o[3]);
        *(float4*)(dst + 4) = make_float4(o[4], o[5], o[6], o[7]);
    }
}

// ---------------------------------------------------------------------------
// Kernel 2: 512-step recurrence + fused log_softmax (R12/R13 proven, 739us).
// 256 threads, 2 batch rows per CTA (grid 128). Thread t = output o.
//   W_hh[o][0..192)   -> 192 registers (96 ull j-pairs)
//   W_hh[o][192..256) -> smem (16 ulonglong2/thread, lane-consecutive)
// Phased step; tanh.approx; ONE barrier per step.
// ---------------------------------------------------------------------------
__global__ void __launch_bounds__(256, 1) rnn_kernel(
    const float* __restrict__ W_hh, float* __restrict__ out)
{
    extern __shared__ __align__(16) float sm[];
    ulonglong2* Wsm = (ulonglong2*)sm;   // [16][256] ulonglong2 = 64 KB
    float* hbuf = sm + 16384;            // [2 buf][2 row][256] = 1024 floats
    float* red  = hbuf + 1024;           // [256]

    const int t  = threadIdx.x;          // = output index o
    const int b0 = blockIdx.x * 2;

    const ulonglong2* wr = (const ulonglong2*)(W_hh + (size_t)t * H_DIM);

    ull Wp[96];
#pragma unroll
    for (int c = 0; c < 48; c++) {
        ulonglong2 v = wr[c];
        Wp[2 * c] = v.x; Wp[2 * c + 1] = v.y;
    }
#pragma unroll
    for (int c = 0; c < 16; c++) Wsm[c * 256 + t] = wr[48 + c];

    hbuf[t] = 0.0f;
    hbuf[256 + t] = 0.0f;
    __syncthreads();

    const float* xpA = g_xproj + (size_t)b0 * H_DIM + t;
    const float* xpB = xpA + H_DIM;
    float xvA = xpA[0];
    float xvB = xpB[0];

    for (int s = 0; s < S_LEN; s++) {
        float xnA = 0.0f, xnB = 0.0f;
        if (s + 1 < S_LEN) {
            size_t off = (size_t)(s + 1) * (B_SZ * H_DIM);
            xnA = xpA[off];
            xnB = xpB[off];
        }

        const ulonglong2* hA = (const ulonglong2*)(hbuf + (s & 1) * 512);
        const ulonglong2* hB = (const ulonglong2*)(hbuf + (s & 1) * 512 + 256);
        float* hn = hbuf + ((s + 1) & 1) * 512;

        ull a0 = 0ULL, a1 = 0ULL, a2 = 0ULL, a3 = 0ULL;

        // row A, register-W j in [0,192)
#pragma unroll
        for (int c = 0; c < 48; c++) {
            ulonglong2 ha = hA[c];
            ffma2(a0, Wp[2 * c],     ha.x);
            ffma2(a1, Wp[2 * c + 1], ha.y);
        }
        // shared smem-W section, j in [192,256): both rows, Wsm read once
#pragma unroll
        for (int c = 0; c < 16; c++) {
            ulonglong2 wv = Wsm[c * 256 + t];
            ulonglong2 ha = hA[48 + c];
            ulonglong2 hb = hB[48 + c];
            ffma2(a0, wv.x, ha.x);
            ffma2(a1, wv.y, ha.y);
            ffma2(a2, wv.x, hb.x);
            ffma2(a3, wv.y, hb.y);
        }
        // finalize row A — MUFU tanh overlaps row-B section
        {
            float2 f0 = as_f2(a0), f1 = as_f2(a1);
            float hnA = tanh_fast(xvA + ((f0.x + f0.y) + (f1.x + f1.y)));
            hn[t] = hnA;
        }
        // row B, register-W j in [0,192)
#pragma unroll
        for (int c = 0; c < 48; c++) {
            ulonglong2 hb = hB[c];
            ffma2(a2, Wp[2 * c],     hb.x);
            ffma2(a3, Wp[2 * c + 1], hb.y);
        }
        {
            float2 f2 = as_f2(a2), f3 = as_f2(a3);
            float hnB = tanh_fast(xvB + ((f2.x + f2.y) + (f3.x + f3.y)));
            hn[256 + t] = hnB;
        }
        __syncthreads();

        xvA = xnA;
        xvB = xnB;
    }

    // Final h in buffer 0. Fused log_softmax per row.
    for (int r = 0; r < 2; r++) {
        float x = hbuf[r * 256 + t];

        red[t] = x;
        __syncthreads();
        for (int off = 128; off > 0; off >>= 1) {
            if (t < off) red[t] = fmaxf(red[t], red[t + off]);
            __syncthreads();
        }
        float mx = red[0];
        __syncthreads();

        red[t] = expf(x - mx);
        __syncthreads();
        for (int off = 128; off > 0; off >>= 1) {
            if (t < off) red[t] = red[t] + red[t + off];
            __syncthreads();
        }
        float lse = logf(red[0]);
        __syncthreads();

        out[(size_t)(b0 + r) * H_DIM + t] = x - mx - lse;
    }
}

extern "C" void kernel_launch(void* const* d_in, const int* in_sizes, int n_in,
                              void* d_out, int out_size)
{
    const int*   X    = (const int*)d_in[0];
    const float* emb  = (const float*)d_in[1];
    const float* W_ih = (const float*)d_in[2];
    const float* W_hh = (const float*)d_in[3];
    const float* b_ih = (const float*)d_in[4];
    const float* b_hh = (const float*)d_in[5];
    float* out = (float*)d_out;

    const int smem_xproj = (64 * 128 * 2) * 4 + 128 * 4;      // 66048 B -> 2 CTAs/SM
    const int smem_rnn   = 16384 * 4 + (1024 + 256) * 4;      // 70656 B
    cudaFuncSetAttribute(xproj_kernel, cudaFuncAttributeMaxDynamicSharedMemorySize, smem_xproj);
    cudaFuncSetAttribute(rnn_kernel,   cudaFuncAttributeMaxDynamicSharedMemorySize, smem_rnn);

    dim3 xgrid((S_LEN * B_SZ) / 128, 2);
    xproj_kernel<<<xgrid, 256, smem_xproj>>>(X, emb, W_ih, b_ih, b_hh);
    rnn_kernel<<<B_SZ / 2, 256, smem_rnn>>>(W_hh, out);
}

// round 16
// speedup vs baseline: 1.2864x; 1.2803x over previous
#include <cuda_runtime.h>
#include <math.h>
#include <string.h>

#define S_LEN 512
#define B_SZ  256
#define E_DIM 128
#define H_DIM 256

static __device__ float g_xproj[(size_t)S_LEN * B_SZ * H_DIM];

typedef unsigned long long ull;

__device__ __forceinline__ void ffma2(ull& d, ull a, ull b) {
    asm("fma.rn.f32x2 %0, %1, %2, %0;" : "+l"(d) : "l"(a), "l"(b));
}
__device__ __forceinline__ ull dup2(float w) {
    ull p;
    asm("mov.b64 %0, {%1, %1};" : "=l"(p) : "f"(w));
    return p;
}
__device__ __forceinline__ float2 as_f2(ull v) {
    float f0, f1;
    asm("mov.b64 {%0, %1}, %2;" : "=f"(f0), "=f"(f1) : "l"(v));
    return make_float2(f0, f1);
}
__device__ __forceinline__ float tanh_fast(float x) {
    float y;
    asm("tanh.approx.f32 %0, %1;" : "=f"(y) : "f"(x));
    return y;
}

// ---------------------------------------------------------------------------
// Kernel 1: fused gather + input projection, 128x128-tile GEMM, K staged in
// two 64-chunks (66 KB smem). 256 threads, 8x8 fragment each. (proven)
// ---------------------------------------------------------------------------
__global__ void __launch_bounds__(256, 2) xproj_kernel(
    const int* __restrict__ X, const float* __restrict__ emb,
    const float* __restrict__ W_ih, const float* __restrict__ b_ih,
    const float* __restrict__ b_hh)
{
    extern __shared__ __align__(16) float xsm[];
    float* As = xsm;                  // [kk][m] 64x128
    float* Bs = xsm + 64 * 128;       // [kk][n] 64x128
    int*   ids = (int*)(Bs + 64 * 128);

    const int t  = threadIdx.x;
    const int m0 = blockIdx.x * 128;
    const int n0 = blockIdx.y * 128;

    if (t < 128) ids[t] = X[m0 + t];
    __syncthreads();

    const int tx = t & 15, ty = t >> 4;

    ull acc[32];
#pragma unroll
    for (int i = 0; i < 32; i++) acc[i] = 0ULL;

    for (int kc = 0; kc < 2; kc++) {
#pragma unroll
        for (int it = 0; it < 4; it++) {
            int idx = t + 256 * it;
            int rr = idx & 127, q16 = idx >> 7;          // q16: 0..7
            float4 fa = ((const float4*)(emb + (size_t)ids[rr] * E_DIM))[kc * 16 + q16];
            As[(4 * q16 + 0) * 128 + rr] = fa.x;
            As[(4 * q16 + 1) * 128 + rr] = fa.y;
            As[(4 * q16 + 2) * 128 + rr] = fa.z;
            As[(4 * q16 + 3) * 128 + rr] = fa.w;
            float4 fa2 = ((const float4*)(emb + (size_t)ids[rr] * E_DIM))[kc * 16 + q16 + 8];
            As[(4 * (q16 + 8) + 0) * 128 + rr] = fa2.x;
            As[(4 * (q16 + 8) + 1) * 128 + rr] = fa2.y;
            As[(4 * (q16 + 8) + 2) * 128 + rr] = fa2.z;
            As[(4 * (q16 + 8) + 3) * 128 + rr] = fa2.w;
            float4 fb = ((const float4*)(W_ih + (size_t)(n0 + rr) * E_DIM))[kc * 16 + q16];
            Bs[(4 * q16 + 0) * 128 + rr] = fb.x;
            Bs[(4 * q16 + 1) * 128 + rr] = fb.y;
            Bs[(4 * q16 + 2) * 128 + rr] = fb.z;
            Bs[(4 * q16 + 3) * 128 + rr] = fb.w;
            float4 fb2 = ((const float4*)(W_ih + (size_t)(n0 + rr) * E_DIM))[kc * 16 + q16 + 8];
            Bs[(4 * (q16 + 8) + 0) * 128 + rr] = fb2.x;
            Bs[(4 * (q16 + 8) + 1) * 128 + rr] = fb2.y;
            Bs[(4 * (q16 + 8) + 2) * 128 + rr] = fb2.z;
            Bs[(4 * (q16 + 8) + 3) * 128 + rr] = fb2.w;
        }
        __syncthreads();

#pragma unroll 4
        for (int k = 0; k < 64; k++) {
            float4 a0 = *(const float4*)(As + k * 128 + ty * 8);
            float4 a1 = *(const float4*)(As + k * 128 + ty * 8 + 4);
            ulonglong2 bl = *(const ulonglong2*)(Bs + k * 128 + tx * 8);
            ulonglong2 bh = *(const ulonglong2*)(Bs + k * 128 + tx * 8 + 4);
            float am[8] = {a0.x, a0.y, a0.z, a0.w, a1.x, a1.y, a1.z, a1.w};
#pragma unroll
            for (int m = 0; m < 8; m++) {
                ull ad = dup2(am[m]);
                ffma2(acc[m * 4 + 0], bl.x, ad);
                ffma2(acc[m * 4 + 1], bl.y, ad);
                ffma2(acc[m * 4 + 2], bh.x, ad);
                ffma2(acc[m * 4 + 3], bh.y, ad);
            }
        }
        __syncthreads();
    }

    float bias[8];
#pragma unroll
    for (int j = 0; j < 8; j++) {
        int n = n0 + tx * 8 + j;
        bias[j] = b_ih[n] + b_hh[n];
    }
#pragma unroll
    for (int m = 0; m < 8; m++) {
        float o[8];
#pragma unroll
        for (int p = 0; p < 4; p++) {
            float2 f = as_f2(acc[m * 4 + p]);
            o[2 * p]     = f.x + bias[2 * p];
            o[2 * p + 1] = f.y + bias[2 * p + 1];
        }
        float* dst = g_xproj + (size_t)(m0 + ty * 8 + m) * H_DIM + n0 + tx * 8;
        *(float4*)(dst)     = make_float4(o[0], o[1], o[2], o[3]);
        *(float4*)(dst + 4) = make_float4(o[4], o[5], o[6], o[7]);
    }
}

// ---------------------------------------------------------------------------
// Kernel 2: 512-step recurrence + fused log_softmax.
// 256 threads, 2 batch rows per CTA (grid 128).
// Output-blocked: thread (io = t&63, jg = t>>6) computes partials for
// 4 outputs {io, io+64, io+128, io+192} over j-slice [64jg, 64jg+64),
// both rows -> each h value is reused 4x (h crossbar traffic /4).
//   W rows io, io+64, io+128 (slice) -> 96 ull regs (192 floats)
//   W row io+192 (slice)            -> smem (16 ulonglong2, lane-distinct)
// Partials exchanged via smem (aligned float4 reads); finalize thread t
// owns output o=t (p=t>>6, io=t&63) for both rows. Two barriers/step.
// ---------------------------------------------------------------------------
__global__ void __launch_bounds__(256, 1) rnn_kernel(
    const float* __restrict__ W_hh, float* __restrict__ out)
{
    extern __shared__ __align__(16) float sm[];
    ulonglong2* Wsm = (ulonglong2*)sm;   // [16][256] ulonglong2 = 64 KB
    float* hbuf = sm + 16384;            // [2 buf][2 row][256] = 1024 floats
    float* part = hbuf + 1024;           // [2 r][4 p][64 io][4 jg] = 2048 floats
    float* red  = part + 2048;           // [256]

    const int t  = threadIdx.x;
    const int io = t & 63;
    const int jg = t >> 6;               // warp-uniform (64 threads per jg)
    const int b0 = blockIdx.x * 2;

    // W rows io, io+64, io+128 (slice [64jg,64jg+64)) -> registers
    ull Wp[96];
#pragma unroll
    for (int p = 0; p < 3; p++) {
        const ulonglong2* w = (const ulonglong2*)(W_hh + (size_t)(io + 64 * p) * H_DIM + 64 * jg);
#pragma unroll
        for (int c = 0; c < 16; c++) {
            ulonglong2 v = w[c];
            Wp[p * 32 + 2 * c]     = v.x;
            Wp[p * 32 + 2 * c + 1] = v.y;
        }
    }
    // W row io+192 (slice) -> smem
    {
        const ulonglong2* w3 = (const ulonglong2*)(W_hh + (size_t)(io + 192) * H_DIM + 64 * jg);
#pragma unroll
        for (int c = 0; c < 16; c++) Wsm[c * 256 + t] = w3[c];
    }

    hbuf[t] = 0.0f;          // buf0 row A
    hbuf[256 + t] = 0.0f;    // buf0 row B
    __syncthreads();

    // finalize mapping: output o = t, rows A and B
    const float* xpA = g_xproj + (size_t)b0 * H_DIM + t;
    const float* xpB = xpA + H_DIM;
    float xvA = xpA[0];
    float xvB = xpB[0];
    const int fp = t >> 6, fio = t & 63;

    for (int s = 0; s < S_LEN; s++) {
        float xnA = 0.0f, xnB = 0.0f;
        if (s + 1 < S_LEN) {
            size_t off = (size_t)(s + 1) * (B_SZ * H_DIM);
            xnA = xpA[off];
            xnB = xpB[off];
        }

        const float* hb = hbuf + (s & 1) * 512;
        const ulonglong2* hA = (const ulonglong2*)(hb + 64 * jg);        // row A slice
        const ulonglong2* hB = (const ulonglong2*)(hb + 256 + 64 * jg);  // row B slice

        ull acc[8];          // [p][r]: acc[p*2+r]
#pragma unroll
        for (int i = 0; i < 8; i++) acc[i] = 0ULL;

#pragma unroll
        for (int c = 0; c < 16; c++) {
            ulonglong2 ha = hA[c];                 // broadcast (warp-uniform)
            ulonglong2 hv = hB[c];                 // broadcast
            ulonglong2 wv = Wsm[c * 256 + t];      // distinct, conflict-free
            // p = 0..2 from registers
            ffma2(acc[0], Wp[0 * 32 + 2 * c], ha.x); ffma2(acc[0], Wp[0 * 32 + 2 * c + 1], ha.y);
            ffma2(acc[1], Wp[0 * 32 + 2 * c], hv.x); ffma2(acc[1], Wp[0 * 32 + 2 * c + 1], hv.y);
            ffma2(acc[2], Wp[1 * 32 + 2 * c], ha.x); ffma2(acc[2], Wp[1 * 32 + 2 * c + 1], ha.y);
            ffma2(acc[3], Wp[1 * 32 + 2 * c], hv.x); ffma2(acc[3], Wp[1 * 32 + 2 * c + 1], hv.y);
            ffma2(acc[4], Wp[2 * 32 + 2 * c], ha.x); ffma2(acc[4], Wp[2 * 32 + 2 * c + 1], ha.y);
            ffma2(acc[5], Wp[2 * 32 + 2 * c], hv.x); ffma2(acc[5], Wp[2 * 32 + 2 * c + 1], hv.y);
            // p = 3 from smem
            ffma2(acc[6], wv.x, ha.x); ffma2(acc[6], wv.y, ha.y);
            ffma2(acc[7], wv.x, hv.x); ffma2(acc[7], wv.y, hv.y);
        }

        // write partials: part[((r*4+p)*64 + io)*4 + jg]
#pragma unroll
        for (int p = 0; p < 4; p++) {
            float2 fA = as_f2(acc[p * 2 + 0]);
            float2 fB = as_f2(acc[p * 2 + 1]);
            part[((0 * 4 + p) * 64 + io) * 4 + jg] = fA.x + fA.y;
            part[((1 * 4 + p) * 64 + io) * 4 + jg] = fB.x + fB.y;
        }
        __syncthreads();   // partials visible; h reads done

        // finalize output o = t for both rows (aligned float4 partial reads)
        float4 pA = *(const float4*)(part + ((0 * 4 + fp) * 64 + fio) * 4);
        float4 pB = *(const float4*)(part + ((1 * 4 + fp) * 64 + fio) * 4);
        float hnA = tanh_fast(xvA + ((pA.x + pA.y) + (pA.z + pA.w)));
        float hnB = tanh_fast(xvB + ((pB.x + pB.y) + (pB.z + pB.w)));

        float* hn = hbuf + ((s + 1) & 1) * 512;
        hn[t]       = hnA;
        hn[256 + t] = hnB;
        __syncthreads();   // new h visible

        xvA = xnA;
        xvB = xnB;
    }

    // Final h in buffer 0 (S_LEN even). Fused log_softmax per row.
    for (int r = 0; r < 2; r++) {
        float x = hbuf[r * 256 + t];

        red[t] = x;
        __syncthreads();
        for (int off = 128; off > 0; off >>= 1) {
            if (t < off) red[t] = fmaxf(red[t], red[t + off]);
            __syncthreads();
        }
        float mx = red[0];
        __syncthreads();

        red[t] = expf(x - mx);
        __syncthreads();
        for (int off = 128; off > 0; off >>= 1) {
            if (t < off) red[t] = red[t] + red[t + off];
            __syncthreads();
        }
        float lse = logf(red[0]);
        __syncthreads();

        out[(size_t)(b0 + r) * H_DIM + t] = x - mx - lse;
    }
}

extern "C" void kernel_launch(void* const* d_in, const int* in_sizes, int n_in,
                              void* d_out, int out_size)
{
    const int*   X    = (const int*)d_in[0];
    const float* emb  = (const float*)d_in[1];
    const float* W_ih = (const float*)d_in[2];
    const float* W_hh = (const float*)d_in[3];
    const float* b_ih = (const float*)d_in[4];
    const float* b_hh = (const float*)d_in[5];
    float* out = (float*)d_out;

    const int smem_xproj = (64 * 128 * 2) * 4 + 128 * 4;            // 66048 B
    const int smem_rnn   = 16384 * 4 + (1024 + 2048 + 256) * 4;     // 78848 B
    cudaFuncSetAttribute(xproj_kernel, cudaFuncAttributeMaxDynamicSharedMemorySize, smem_xproj);
    cudaFuncSetAttribute(rnn_kernel,   cudaFuncAttributeMaxDynamicSharedMemorySize, smem_rnn);

    dim3 xgrid((S_LEN * B_SZ) / 128, 2);
    xproj_kernel<<<xgrid, 256, smem_xproj>>>(X, emb, W_ih, b_ih, b_hh);
    rnn_kernel<<<B_SZ / 2, 256, smem_rnn>>>(W_hh, out);
}